// round 17
// baseline (speedup 1.0000x reference)
#include <cuda_runtime.h>
#include <cuda_bf16.h>
#include <math.h>

#define N_TOKENS 131072
#define HIDDEN   1024
#define CL       64
#define EXPERTS  64

// Scratch (allocation-free rule: __device__ globals)
__device__ float g_h[N_TOKENS * CL];       // gelu(xW+b), 32 MB
__device__ float g_cn[EXPERTS * CL];       // normalized centroids
__device__ float g_cc[EXPERTS];            // sum-sq of normalized centroids

// ---------------------------------------------------------------------------
// Eigen/XLA erf (fused pmadd Horner)
// ---------------------------------------------------------------------------
__device__ __forceinline__ float eigen_erf(float x) {
    x = fmaxf(fminf(x, 4.0f), -4.0f);
    float x2 = __fmul_rn(x, x);
    float p = fmaf(x2, -2.72614225801306e-10f, 2.77068142495902e-08f);
    p = fmaf(x2, p, -2.10102402082508e-06f);
    p = fmaf(x2, p, -5.69250639462346e-05f);
    p = fmaf(x2, p, -7.34990630326855e-04f);
    p = fmaf(x2, p, -2.95459980854025e-03f);
    p = fmaf(x2, p, -1.60960333262415e-02f);
    p = __fmul_rn(x, p);
    float q = fmaf(x2, -1.45660718464996e-05f, -2.13374055278905e-04f);
    q = fmaf(x2, q, -1.68282697438203e-03f);
    q = fmaf(x2, q, -7.37332916720468e-03f);
    q = fmaf(x2, q, -1.42647390514189e-02f);
    return __fdiv_rn(p, q);
}

__device__ __forceinline__ float xla_gelu(float v) {
    float t = __fmul_rn(v, __int_as_float(0x3F3504F3));  // * 1/sqrt(2) folded
    float e = eigen_erf(t);
    float r = __fmul_rn(v, __fadd_rn(e, 1.0f));
    return __fmul_rn(r, 0.5f);
}

// XLA:CPU runtime exp (Eigen/Cephes): fused poly, unfused Cody-Waite
__device__ __forceinline__ float xla_exp(float x) {
    x = fminf(x, 88.3762626647950f);
    x = fmaxf(x, -88.3762626647949f);
    float fx = fmaf(x, 1.44269504088896341f, 0.5f);
    fx = floorf(fx);
    float tmp = __fmul_rn(fx, 0.693359375f);
    float z   = __fmul_rn(fx, -2.12194440e-4f);
    x = __fsub_rn(x, tmp);
    x = __fsub_rn(x, z);
    z = __fmul_rn(x, x);
    float y = 1.9875691500E-4f;
    y = fmaf(y, x, 1.3981999507E-3f);
    y = fmaf(y, x, 8.3334519073E-3f);
    y = fmaf(y, x, 4.1665795894E-2f);
    y = fmaf(y, x, 1.6666665459E-1f);
    y = fmaf(y, x, 5.0000001201E-1f);
    y = fmaf(y, z, x);
    y = __fadd_rn(y, 1.0f);
    int n = (int)fx;
    float p2n = __int_as_float((n + 127) << 23);
    return __fmul_rn(y, p2n);
}

// 8-lane strided row-reduce, unfused body, halving horizontal
__device__ __forceinline__ float vsum_sq64(const float* v) {
    float a[8];
    #pragma unroll
    for (int l = 0; l < 8; l++) a[l] = 0.f;
    #pragma unroll
    for (int i = 0; i < 8; i++)
        #pragma unroll
        for (int l = 0; l < 8; l++)
            a[l] = __fadd_rn(a[l], __fmul_rn(v[8 * i + l], v[8 * i + l]));
    float b0 = __fadd_rn(a[0], a[4]);
    float b1 = __fadd_rn(a[1], a[5]);
    float b2 = __fadd_rn(a[2], a[6]);
    float b3 = __fadd_rn(a[3], a[7]);
    return __fadd_rn(__fadd_rn(b0, b2), __fadd_rn(b1, b3));
}

__device__ __forceinline__ float vsum64(const float* v) {
    float a[8];
    #pragma unroll
    for (int l = 0; l < 8; l++) a[l] = 0.f;
    #pragma unroll
    for (int i = 0; i < 8; i++)
        #pragma unroll
        for (int l = 0; l < 8; l++)
            a[l] = __fadd_rn(a[l], v[8 * i + l]);
    float b0 = __fadd_rn(a[0], a[4]);
    float b1 = __fadd_rn(a[1], a[5]);
    float b2 = __fadd_rn(a[2], a[6]);
    float b3 = __fadd_rn(a[3], a[7]);
    return __fadd_rn(__fadd_rn(b0, b2), __fadd_rn(b1, b3));
}

// ---------------------------------------------------------------------------
// Kernel 0: normalize centroids — one expert per block (latency-minimal)
// ---------------------------------------------------------------------------
__global__ void centroid_norm_kernel(const float* __restrict__ centroids) {
    if (threadIdx.x != 0) return;
    int e = blockIdx.x;
    float c[CL];
    for (int j = 0; j < CL; j++) c[j] = centroids[e * CL + j];
    float ss = vsum_sq64(c);
    float nrm = fmaxf(__fsqrt_rn(ss), 1e-8f);
    float cn[CL];
    for (int j = 0; j < CL; j++) {
        cn[j] = __fdiv_rn(c[j], nrm);
        g_cn[e * CL + j] = cn[j];
    }
    g_cc[e] = vsum_sq64(cn);
}

// ---------------------------------------------------------------------------
// Kernel 1: fp32 tiled GEMM  h = gelu(x @ W + b)   [R13, byte-for-byte]
// ---------------------------------------------------------------------------
#define BM 128
#define BN 64
#define BK 16
#define KSEG 512

__global__ __launch_bounds__(256, 2)
void gemm_gelu_kernel(const float* __restrict__ x,
                      const float* __restrict__ W,
                      const float* __restrict__ b) {
    __shared__ float As[BK][BM];
    __shared__ float Bs[BK][BN];

    const int tid = threadIdx.x;
    const int m0  = blockIdx.x * BM;
    const int tn  = tid & 15;
    const int tm  = tid >> 4;

    const int arow = tid >> 2;
    const int ac4  = tid & 3;
    const int brow = tid >> 4;
    const int bc4  = tid & 15;

    float acc[8][4];
    float accp[8][4];
    #pragma unroll
    for (int i = 0; i < 8; i++)
        #pragma unroll
        for (int j = 0; j < 4; j++) { acc[i][j] = 0.f; accp[i][j] = 0.f; }

    for (int k0 = 0; k0 < HIDDEN; k0 += BK) {
        if (k0 == KSEG) {
            #pragma unroll
            for (int i = 0; i < 8; i++)
                #pragma unroll
                for (int j = 0; j < 4; j++) {
                    accp[i][j] = __fadd_rn(accp[i][j], acc[i][j]);
                    acc[i][j] = 0.f;
                }
        }

        float4 a0 = *(const float4*)&x[(size_t)(m0 + arow)      * HIDDEN + k0 + ac4 * 4];
        float4 a1 = *(const float4*)&x[(size_t)(m0 + arow + 64) * HIDDEN + k0 + ac4 * 4];
        float4 bb = *(const float4*)&W[(size_t)(k0 + brow) * CL + bc4 * 4];

        __syncthreads();

        As[ac4 * 4 + 0][arow] = a0.x;
        As[ac4 * 4 + 1][arow] = a0.y;
        As[ac4 * 4 + 2][arow] = a0.z;
        As[ac4 * 4 + 3][arow] = a0.w;
        As[ac4 * 4 + 0][arow + 64] = a1.x;
        As[ac4 * 4 + 1][arow + 64] = a1.y;
        As[ac4 * 4 + 2][arow + 64] = a1.z;
        As[ac4 * 4 + 3][arow + 64] = a1.w;
        *(float4*)&Bs[brow][bc4 * 4] = bb;

        __syncthreads();

        #pragma unroll
        for (int kk = 0; kk < BK; kk++) {
            float af[8], bf[4];
            *(float4*)&af[0] = *(const float4*)&As[kk][tm * 8 + 0];
            *(float4*)&af[4] = *(const float4*)&As[kk][tm * 8 + 4];
            *(float4*)&bf[0] = *(const float4*)&Bs[kk][tn * 4];
            #pragma unroll
            for (int i = 0; i < 8; i++)
                #pragma unroll
                for (int j = 0; j < 4; j++)
                    acc[i][j] = fmaf(af[i], bf[j], acc[i][j]);
        }
    }

    float bias[4];
    #pragma unroll
    for (int j = 0; j < 4; j++) bias[j] = __ldg(&b[tn * 4 + j]);

    #pragma unroll
    for (int i = 0; i < 8; i++) {
        int m = m0 + tm * 8 + i;
        float4 o;
        float v;
        v = __fadd_rn(__fadd_rn(accp[i][0], acc[i][0]), bias[0]); o.x = xla_gelu(v);
        v = __fadd_rn(__fadd_rn(accp[i][1], acc[i][1]), bias[1]); o.y = xla_gelu(v);
        v = __fadd_rn(__fadd_rn(accp[i][2], acc[i][2]), bias[2]); o.z = xla_gelu(v);
        v = __fadd_rn(__fadd_rn(accp[i][3], acc[i][3]), bias[3]); o.w = xla_gelu(v);
        *(float4*)&g_h[(size_t)m * CL + tn * 4] = o;
    }
}

// ---------------------------------------------------------------------------
// Kernel 2: epilogue — smem-staged h tile, precomputed centroids, ILP-4
// expert unroll.  All per-element chains identical to R13 (bit-exact).
// ---------------------------------------------------------------------------
#define EPB 128
// dynamic smem (floats): h_s [128][65]=8320 | cn_s [64][64]=4096 | cc_s 64
#define EPI_SMEM_FLOATS (8320 + 4096 + 64)

__global__ __launch_bounds__(EPB)
void router_epilogue_kernel(float* __restrict__ out) {
    extern __shared__ float sm[];
    float* h_s  = sm;            // [128][65]
    float* cn_s = sm + 8320;     // [64][64]
    float* cc_s = sm + 12416;    // [64]

    const int tid = threadIdx.x;
    const int t0  = blockIdx.x * EPB;

    // coalesced stage of the 128x64 h tile into pad-65 rows
    {
        const float4* src = (const float4*)&g_h[(size_t)t0 * CL];
        #pragma unroll
        for (int it = 0; it < EPB * CL / 4 / EPB; it++) {
            int idx = it * EPB + tid;
            float4 v = src[idx];
            int flat = idx * 4;
            int row  = flat >> 6;
            int col  = flat & 63;
            float* dst = &h_s[row * 65 + col];
            dst[0] = v.x; dst[1] = v.y; dst[2] = v.z; dst[3] = v.w;
        }
    }
    // precomputed centroids -> smem (coalesced)
    {
        const float4* src = (const float4*)g_cn;
        float4* dst = (float4*)cn_s;
        #pragma unroll
        for (int it = 0; it < EXPERTS * CL / 4 / EPB; it++)
            dst[it * EPB + tid] = src[it * EPB + tid];
        if (tid < EXPERTS) cc_s[tid] = g_cc[tid];
    }

    __syncthreads();

    const int t = t0 + tid;

    float d[CL];
    #pragma unroll
    for (int j = 0; j < CL; j++) d[j] = h_s[tid * 65 + j];

    float ss  = vsum_sq64(d);
    float nrm = fmaxf(__fsqrt_rn(ss), 1e-8f);
    #pragma unroll
    for (int j = 0; j < CL; j++) d[j] = __fdiv_rn(d[j], nrm);
    float dd = vsum_sq64(d);

    // pass 1: -dist per expert; 4 experts in flight (independent chains)
    float nd[EXPERTS];
    float ndmax = -INFINITY;
    #pragma unroll 1
    for (int eb = 0; eb < EXPERTS; eb += 4) {
        float dot0 = 0.f, dot1 = 0.f, dot2 = 0.f, dot3 = 0.f;
        const float4* c0 = (const float4*)&cn_s[(eb + 0) * CL];
        const float4* c1 = (const float4*)&cn_s[(eb + 1) * CL];
        const float4* c2 = (const float4*)&cn_s[(eb + 2) * CL];
        const float4* c3 = (const float4*)&cn_s[(eb + 3) * CL];
        #pragma unroll
        for (int jj = 0; jj < CL / 4; jj++) {
            float4 a = c0[jj], b4 = c1[jj], c = c2[jj], e4 = c3[jj];
            float x0 = d[jj * 4 + 0], x1 = d[jj * 4 + 1];
            float x2 = d[jj * 4 + 2], x3 = d[jj * 4 + 3];
            dot0 = fmaf(x0, a.x,  dot0); dot1 = fmaf(x0, b4.x, dot1);
            dot2 = fmaf(x0, c.x,  dot2); dot3 = fmaf(x0, e4.x, dot3);
            dot0 = fmaf(x1, a.y,  dot0); dot1 = fmaf(x1, b4.y, dot1);
            dot2 = fmaf(x1, c.y,  dot2); dot3 = fmaf(x1, e4.y, dot3);
            dot0 = fmaf(x2, a.z,  dot0); dot1 = fmaf(x2, b4.z, dot1);
            dot2 = fmaf(x2, c.z,  dot2); dot3 = fmaf(x2, e4.z, dot3);
            dot0 = fmaf(x3, a.w,  dot0); dot1 = fmaf(x3, b4.w, dot1);
            dot2 = fmaf(x3, c.w,  dot2); dot3 = fmaf(x3, e4.w, dot3);
        }
        float sq0 = __fsub_rn(__fadd_rn(dd, cc_s[eb + 0]), __fmul_rn(2.0f, dot0));
        float sq1 = __fsub_rn(__fadd_rn(dd, cc_s[eb + 1]), __fmul_rn(2.0f, dot1));
        float sq2 = __fsub_rn(__fadd_rn(dd, cc_s[eb + 2]), __fmul_rn(2.0f, dot2));
        float sq3 = __fsub_rn(__fadd_rn(dd, cc_s[eb + 3]), __fmul_rn(2.0f, dot3));
        float v0 = -__fsqrt_rn(fmaxf(sq0, 0.0f));
        float v1 = -__fsqrt_rn(fmaxf(sq1, 0.0f));
        float v2 = -__fsqrt_rn(fmaxf(sq2, 0.0f));
        float v3 = -__fsqrt_rn(fmaxf(sq3, 0.0f));
        nd[eb + 0] = v0; nd[eb + 1] = v1; nd[eb + 2] = v2; nd[eb + 3] = v3;
        ndmax = fmaxf(ndmax, fmaxf(fmaxf(v0, v1), fmaxf(v2, v3)));
    }

    // pass 2: w = exp(x - xmax)
    #pragma unroll
    for (int e = 0; e < EXPERTS; e++)
        nd[e] = xla_exp(__fsub_rn(nd[e], ndmax));
    float sum = vsum64(nd);

    // pass 3: p = w / sum, stable top-2 (ties -> lower index)
    float p1 = -1.f, p2 = -1.f;
    int   i1 = 0,    i2 = 0;
    for (int e = 0; e < EXPERTS; e++) {
        float p = __fdiv_rn(nd[e], sum);
        if (p > p1)      { p2 = p1; i2 = i1; p1 = p; i1 = e; }
        else if (p > p2) { p2 = p; i2 = e; }
    }

    out[(size_t)t * 2 + 0] = p1;
    out[(size_t)t * 2 + 1] = p2;
    float* oi = out + (size_t)N_TOKENS * 2;
    oi[(size_t)t * 2 + 0] = (float)i1;
    oi[(size_t)t * 2 + 1] = (float)i2;
}

// ---------------------------------------------------------------------------
extern "C" void kernel_launch(void* const* d_in, const int* in_sizes, int n_in,
                              void* d_out, int out_size) {
    const float* x         = (const float*)d_in[0];
    const float* W         = (const float*)d_in[1];
    const float* b         = (const float*)d_in[2];
    const float* centroids = (const float*)d_in[3];
    float* out = (float*)d_out;

    centroid_norm_kernel<<<EXPERTS, 32>>>(centroids);
    gemm_gelu_kernel<<<N_TOKENS / BM, 256>>>(x, W, b);

    cudaFuncSetAttribute(router_epilogue_kernel,
                         cudaFuncAttributeMaxDynamicSharedMemorySize,
                         EPI_SMEM_FLOATS * (int)sizeof(float));
    router_epilogue_kernel<<<N_TOKENS / EPB, EPB,
                             EPI_SMEM_FLOATS * sizeof(float)>>>(out);
}